// round 13
// baseline (speedup 1.0000x reference)
#include <cuda_runtime.h>

// ---------------------------------------------------------------------------
// BilateralDenoiser: 15x15 cross-bilateral filter (SIGMA=1 -> N=7, 225 taps)
//   w = exp(-d^2/2) * clip(nrm_t . nrm_c, eps, 1)^128
//       * exp(-|z_t - z_c| / max(dz_c * d, eps)),  zero outside image.
// R10: issue-bound at 82% with occupancy capped at 24 warps by the 72.5KB
//      smem tile. Drop the tile: padded global SoA arrays + __ldg (zero pad
//      => weight exactly 0 via lg2(0) = -inf), tiny table in static smem,
//      __launch_bounds__(256,4) -> 32 warps/SM.
// ---------------------------------------------------------------------------

#define IH 1080
#define IW 1920
#define ICH 11
#define PAD 7
#define PW (IW + 14)          // 1934
#define PH (7 + 1088 + 7)     // 1102: bottom pad covers grid-y overrun + halo
#define TILE 32
#define NROWS 18              // PY + 14, PY = 4
#define TABN (20 * 15)        // 300 entries: s in [0,19], dx in [0,14]
#define FEPS 1e-4f
#define RDEN_CLAMP 14426.950408889634f   // 1e4 * log2(e)
#define F32_INF __int_as_float(0x7f800000)

__device__ float4 g_A[PH * PW];  // nrm.x, nrm.y, nrm.z, z      (padded, zeros)
__device__ float4 g_B[PH * PW];  // col.r, col.g, col.b, rr(=log2e/dz or +inf)

// ---------------- helpers ---------------------------------------------------
__device__ __forceinline__ unsigned long long pk(float lo, float hi) {
    unsigned long long r;
    asm("mov.b64 %0, {%1, %2};" : "=l"(r)
        : "r"(__float_as_uint(lo)), "r"(__float_as_uint(hi)));
    return r;
}
__device__ __forceinline__ void upk(unsigned long long v, float& lo, float& hi) {
    unsigned int a, b;
    asm("mov.b64 {%0, %1}, %2;" : "=r"(a), "=r"(b) : "l"(v));
    lo = __uint_as_float(a); hi = __uint_as_float(b);
}
__device__ __forceinline__ unsigned long long f2add(unsigned long long a, unsigned long long b) {
    unsigned long long d;
    asm("add.rn.f32x2 %0, %1, %2;" : "=l"(d) : "l"(a), "l"(b));
    return d;
}
__device__ __forceinline__ unsigned long long f2fma(unsigned long long a, unsigned long long b,
                                                    unsigned long long c) {
    unsigned long long d;
    asm("fma.rn.f32x2 %0, %1, %2, %3;" : "=l"(d) : "l"(a), "l"(b), "l"(c));
    return d;
}
__device__ __forceinline__ float rcpa(float x) {
    float y; asm("rcp.approx.f32 %0, %1;" : "=f"(y) : "f"(x)); return y;
}
__device__ __forceinline__ float ex2a(float x) {
    float y; asm("ex2.approx.f32 %0, %1;" : "=f"(y) : "f"(x)); return y;
}
__device__ __forceinline__ float lg2a(float x) {
    float y; asm("lg2.approx.f32 %0, %1;" : "=f"(y) : "f"(x)); return y;
}

// ---------------- repack: AoS(11ch) -> padded float4 SoA ---------------------
__global__ void repack_kernel(const float* __restrict__ in) {
    int i = blockIdx.x * blockDim.x + threadIdx.x;
    if (i >= PH * PW) return;
    int py = i / PW, px = i - py * PW;
    int y = py - PAD, x = px - PAD;
    float4 a = make_float4(0.f, 0.f, 0.f, 0.f);
    float4 b = a;
    if ((unsigned)y < (unsigned)IH && (unsigned)x < (unsigned)IW) {
        const float* p = in + ((size_t)y * IW + x) * ICH;
        float dz = p[10];
        float rr = (dz > 0.0f) ? rcpa(dz) * 1.4426950408889634f : F32_INF;
        a = make_float4(p[3], p[4], p[5], p[9]);
        b = make_float4(p[0], p[1], p[2], rr);
    }
    g_A[i] = a; g_B[i] = b;
}

// ---------------- main kernel: 32x32 outputs / CTA, PY=4 per thread ---------
__global__ void __launch_bounds__(256, 4)
bilateral_kernel(float* __restrict__ out) {
    __shared__ float4 sTab[TABN];   // {cxyA, cxyB, rdA, rdB} per (s,dx)

    const int tix  = threadIdx.x;
    const int tidy = threadIdx.y;
    const int tid  = tidy * 32 + tix;

    // per-(dy,dx) table. entry s covers lane pair (dyA=s-9, dyB=s-10).
    //   cxy = -(dy^2+dx^2)*log2e/2   (-1e30 kills weight when |dy|>7)
    //   rd  = 1/dist (1e4 at dist=0 center tap; fmin clamp absorbs it)
    for (int i = tid; i < TABN; i += 256) {
        int s = i / 15, dxi = i - s * 15;
        float dx = (float)(dxi - 7);
        int dyA = s - 9, dyB = s - 10;
        float qA = dyA * dyA + dx * dx, qB = dyB * dyB + dx * dx;
        bool vA = (dyA >= -7) && (dyA <= 7);
        bool vB = (dyB >= -7) && (dyB <= 7);
        float cA = vA ? -qA * 0.72134752044f : -1e30f;
        float cB = vB ? -qB * 0.72134752044f : -1e30f;
        float rA = vA ? rsqrtf(qA) : 1e4f;
        float rB = vB ? rsqrtf(qB) : 1e4f;
        sTab[i] = make_float4(cA, cB, rA, rB);
    }
    __syncthreads();

    // centers: 4 rows per thread. gy = blockIdx.y*32 + tidy*4 + c, gx as below.
    const int tidy4 = tidy * 4;
    const int gx    = blockIdx.x * TILE + tix;
    const int gyb   = blockIdx.y * TILE + tidy4;

    float cnx[4], cny[4], cnz[4], cz[4], crr[4];
#pragma unroll
    for (int c = 0; c < 4; ++c) {
        int pidx = (gyb + c + PAD) * PW + gx + PAD;
        float4 a = __ldg(&g_A[pidx]);
        cnx[c] = a.x; cny[c] = a.y; cnz[c] = a.z; cz[c] = a.w;
        crr[c] = __ldg(&g_B[pidx]).w;
    }
    unsigned long long ar2[2] = {0ull, 0ull}, ag2[2] = {0ull, 0ull};
    unsigned long long ab2[2] = {0ull, 0ull}, aw2[2] = {0ull, 0ull};

    // neighbor index: (gyb + nyi) * PW + (gx + dxi)   [pads cancel: -7+7]
    const int nbase = gyb * PW + gx;
#pragma unroll 1
    for (int dxi = 0; dxi < 15; ++dxi) {
#pragma unroll 3
        for (int nyi = 0; nyi < NROWS; ++nyi) {
            int idx = nbase + nyi * PW + dxi;
            float4 a = __ldg(&g_A[idx]);        // nx, ny, nz, z
            float4 b = __ldg(&g_B[idx]);        // r, g, b, (rr unused)
            unsigned long long cr2 = pk(b.x, b.x);
            unsigned long long cg2 = pk(b.y, b.y);
            unsigned long long cb2 = pk(b.z, b.z);
            float4 T0 = sTab[(nyi + 2) * 15 + dxi];  // pair 0: dy = nyi-7, nyi-8
            float4 T1 = sTab[nyi * 15 + dxi];        // pair 1: dy = nyi-9, nyi-10

            float w[4];
#pragma unroll
            for (int p = 0; p < 2; ++p) {
                const float4& T = p ? T1 : T0;
#pragma unroll
                for (int l = 0; l < 2; ++l) {
                    int c = 2 * p + l;
                    // normal term: 128*lg2(clamp(dot,0,1)); lg2(0)=-inf => w=0
                    float d = fmaf(a.z, cnz[c], fmaf(a.y, cny[c], a.x * cnx[c]));
                    float s = fminf(fmaxf(d, 0.0f), 1.0f);
                    float lg = lg2a(s);
                    // depth term: |z_t - z_c| * min(rr_c * (1/dist), 1e4*log2e)
                    float t    = fabsf(a.w - cz[c]);
                    float rden = fminf(crr[c] * (l ? T.w : T.z), RDEN_CLAMP);
                    // w = exp2( cxy + 128*lg - t*rden )
                    float arg = fmaf(lg, 128.0f, l ? T.y : T.x);
                    arg = fmaf(-t, rden, arg);
                    w[c] = ex2a(arg);
                }
                unsigned long long w2 = pk(w[2 * p], w[2 * p + 1]);
                aw2[p] = f2add(aw2[p], w2);
                ar2[p] = f2fma(cr2, w2, ar2[p]);
                ag2[p] = f2fma(cg2, w2, ag2[p]);
                ab2[p] = f2fma(cb2, w2, ab2[p]);
            }
        }
    }

    // write out: out[(gy*W+gx)*3 + ch] = acc_col / max(acc_w, eps)
#pragma unroll
    for (int p = 0; p < 2; ++p) {
        float w0, w1, r0, r1, q0, q1, b0, b1;
        upk(aw2[p], w0, w1);
        upk(ar2[p], r0, r1);
        upk(ag2[p], q0, q1);
        upk(ab2[p], b0, b1);
        int gy = gyb + 2 * p;
        if (gy < IH) {
            float inv = rcpa(fmaxf(w0, FEPS));
            float* o = out + ((size_t)gy * IW + gx) * 3;
            o[0] = r0 * inv; o[1] = q0 * inv; o[2] = b0 * inv;
        }
        if (gy + 1 < IH) {
            float inv = rcpa(fmaxf(w1, FEPS));
            float* o = out + ((size_t)(gy + 1) * IW + gx) * 3;
            o[0] = r1 * inv; o[1] = q1 * inv; o[2] = b1 * inv;
        }
    }
}

extern "C" void kernel_launch(void* const* d_in, const int* in_sizes, int n_in,
                              void* d_out, int out_size) {
    (void)in_sizes; (void)n_in; (void)out_size;
    const float* in = (const float*)d_in[0];
    float* out = (float*)d_out;

    repack_kernel<<<(PH * PW + 255) / 256, 256>>>(in);

    dim3 blk(32, 8);
    dim3 grd(IW / TILE, (IH + TILE - 1) / TILE);
    bilateral_kernel<<<grd, blk>>>(out);
}

// round 14
// speedup vs baseline: 1.5160x; 1.5160x over previous
#include <cuda_runtime.h>

// ---------------------------------------------------------------------------
// BilateralDenoiser: 15x15 cross-bilateral filter (SIGMA=1 -> N=7, 225 taps)
//   w = exp(-d^2/2) * clip(nrm_t . nrm_c, eps, 1)^128
//       * exp(-|z_t - z_c| / max(dz_c * d, eps)),  zero outside image.
// R13 post-mortem: LDG path regressed (issue 82->78, long-scoreboard); revert
//      to smem tile.
// R14: disc truncation. Taps with q=dy^2+dx^2 > 40 have w_xy <= 2e-9 -> drop
//      (error << 1e-3 budget). 129/225 taps kept; per-dx row windows on the
//      pair loop: 270 -> 136 inner iterations. Halo 7->6 (SWID 44).
//      Also fold the dot clamp into fma.rn.sat.
// ---------------------------------------------------------------------------

#define IH 1080
#define IW 1920
#define ICH 11
#define TILE 32
#define HALO 6
#define SWID 44          // TILE + 2*HALO
#define TABN (18 * 15)   // s in [0,17], dx slot in [0,14]
#define FEPS 1e-4f
#define QMAX 40
#define RDEN_CLAMP 14426.950408889634f   // 1e4 * log2(e)
#define F32_INF __int_as_float(0x7f800000)

__device__ float4 g_A[IH * IW];  // nrm.x, nrm.y, nrm.z, z
__device__ float4 g_B[IH * IW];  // col.r, col.g, col.b, rr (= log2e/dz or +inf)

// ---------------- helpers ---------------------------------------------------
__device__ __forceinline__ unsigned long long pk(float lo, float hi) {
    unsigned long long r;
    asm("mov.b64 %0, {%1, %2};" : "=l"(r)
        : "r"(__float_as_uint(lo)), "r"(__float_as_uint(hi)));
    return r;
}
__device__ __forceinline__ void upk(unsigned long long v, float& lo, float& hi) {
    unsigned int a, b;
    asm("mov.b64 {%0, %1}, %2;" : "=r"(a), "=r"(b) : "l"(v));
    lo = __uint_as_float(a); hi = __uint_as_float(b);
}
__device__ __forceinline__ unsigned long long f2add(unsigned long long a, unsigned long long b) {
    unsigned long long d;
    asm("add.rn.f32x2 %0, %1, %2;" : "=l"(d) : "l"(a), "l"(b));
    return d;
}
__device__ __forceinline__ unsigned long long f2fma(unsigned long long a, unsigned long long b,
                                                    unsigned long long c) {
    unsigned long long d;
    asm("fma.rn.f32x2 %0, %1, %2, %3;" : "=l"(d) : "l"(a), "l"(b), "l"(c));
    return d;
}
__device__ __forceinline__ float fma_sat(float a, float b, float c) {
    float d;
    asm("fma.rn.sat.f32 %0, %1, %2, %3;" : "=f"(d) : "f"(a), "f"(b), "f"(c));
    return d;
}
__device__ __forceinline__ float rcpa(float x) {
    float y; asm("rcp.approx.f32 %0, %1;" : "=f"(y) : "f"(x)); return y;
}
__device__ __forceinline__ float ex2a(float x) {
    float y; asm("ex2.approx.f32 %0, %1;" : "=f"(y) : "f"(x)); return y;
}
__device__ __forceinline__ float lg2a(float x) {
    float y; asm("lg2.approx.f32 %0, %1;" : "=f"(y) : "f"(x)); return y;
}

// ---------------- repack: AoS(11ch) -> two float4 SoA buffers ----------------
__global__ void repack_kernel(const float* __restrict__ in) {
    int i = blockIdx.x * blockDim.x + threadIdx.x;
    if (i >= IH * IW) return;
    const float* p = in + (size_t)i * ICH;
    float dz = p[10];
    float rr = (dz > 0.0f) ? rcpa(dz) * 1.4426950408889634f : F32_INF;
    g_A[i] = make_float4(p[3], p[4], p[5], p[9]);
    g_B[i] = make_float4(p[0], p[1], p[2], rr);
}

// ---------------- main tiled kernel: 32x32 outputs / CTA, PY=4 per thread ---
__global__ void __launch_bounds__(256)
bilateral_kernel(float* __restrict__ out) {
    extern __shared__ unsigned char smraw[];
    float4* sA   = reinterpret_cast<float4*>(smraw);
    float4* sB   = sA + SWID * SWID;
    float4* sTab = sB + SWID * SWID;   // {cxyA, cxyB, rdA, rdB} per (s,dx)

    const int tix  = threadIdx.x;
    const int tidy = threadIdx.y;
    const int tid  = tidy * 32 + tix;
    const int gx0  = blockIdx.x * TILE - HALO;
    const int gy0  = blockIdx.y * TILE - HALO;

    // fill 44x44 halo tile; OOB pixels -> zeros (nrm=0 => weight exactly 0)
    for (int i = tid; i < SWID * SWID; i += 256) {
        int ly = i / SWID, lx = i - ly * SWID;
        int gy = gy0 + ly, gx = gx0 + lx;
        float4 a = make_float4(0.f, 0.f, 0.f, 0.f);
        float4 b = a;
        if ((unsigned)gy < (unsigned)IH && (unsigned)gx < (unsigned)IW) {
            int g = gy * IW + gx;
            a = g_A[g]; b = g_B[g];
        }
        sA[i] = a; sB[i] = b;
    }
    // per-(s,dx) table. entry s covers lane pair (dyA=s-8, dyB=s-9).
    //   cxy = -q*log2e/2  (q = dy^2+dx^2), or -1e30 (kills weight) if q>QMAX
    //   rd  = 1/dist (1e4 at dist=0 center tap; fmin clamp absorbs it)
    for (int i = tid; i < TABN; i += 256) {
        int s = i / 15, dxi = i - s * 15;
        float dx = (float)(dxi - 7);
        int dyA = s - 8, dyB = s - 9;
        float qA = dyA * dyA + dx * dx, qB = dyB * dyB + dx * dx;
        bool vA = qA <= (float)QMAX;
        bool vB = qB <= (float)QMAX;
        float cA = vA ? -qA * 0.72134752044f : -1e30f;
        float cB = vB ? -qB * 0.72134752044f : -1e30f;
        float rA = (vA && qA > 0.f) ? rsqrtf(qA) : 1e4f;
        float rB = (vB && qB > 0.f) ? rsqrtf(qB) : 1e4f;
        sTab[i] = make_float4(cA, cB, rA, rB);
    }
    __syncthreads();

    // center data for 4 rows: c = 0..3 (pair p holds centers 2p, 2p+1)
    const int tidy4 = tidy * 4;
    float cnx[4], cny[4], cnz[4], cz[4], crr[4];
#pragma unroll
    for (int c = 0; c < 4; ++c) {
        int r = tidy4 + c + HALO;
        float4 a = sA[r * SWID + tix + HALO];
        cnx[c] = a.x; cny[c] = a.y; cnz[c] = a.z; cz[c] = a.w;
        crr[c] = sB[r * SWID + tix + HALO].w;
    }
    unsigned long long ar2[2] = {0ull, 0ull}, ag2[2] = {0ull, 0ull};
    unsigned long long ab2[2] = {0ull, 0ull}, aw2[2] = {0ull, 0ull};

    // disc windows: dymax(|dx|) for q <= 40; rows nyi in [HALO-dymax, ...),
    // ntrip = 2*dymax+4 (covers the 4-lane dy footprint {nyi-6..nyi-9}).
    // dxi = 1..13 (dx = -6..6); dx = +-7 columns are entirely outside the disc.
    const int rowbase = tidy4 * SWID + tix;
#pragma unroll 1
    for (int dxi = 1; dxi <= 13; ++dxi) {
        int adx = (dxi >= 7) ? dxi - 7 : 7 - dxi;       // |dx| in 0..6
        // dymax lut: |dx| 0,1,2 -> 6; 3 -> 5; 4 -> 4; 5 -> 3; 6 -> 2
        int dymax = (adx <= 2) ? 6 : (8 - adx);
        int ylo   = HALO - dymax;
        int ntrip = 2 * dymax + 4;
#pragma unroll 2
        for (int k = 0; k < ntrip; ++k) {
            int nyi = ylo + k;
            int idx = rowbase + nyi * SWID + (dxi - 1);
            float4 a = sA[idx];                 // nx, ny, nz, z
            float4 b = sB[idx];                 // r, g, b, (rr unused)
            unsigned long long cr2 = pk(b.x, b.x);
            unsigned long long cg2 = pk(b.y, b.y);
            unsigned long long cb2 = pk(b.z, b.z);
            float4 T0 = sTab[(nyi + 2) * 15 + dxi];  // pair 0: dy = nyi-6, nyi-7
            float4 T1 = sTab[nyi * 15 + dxi];        // pair 1: dy = nyi-8, nyi-9

            float w[4];
#pragma unroll
            for (int p = 0; p < 2; ++p) {
                const float4& T = p ? T1 : T0;
#pragma unroll
                for (int l = 0; l < 2; ++l) {
                    int c = 2 * p + l;
                    // normal term: 128*lg2(sat(dot)); sat->0 => lg2->-inf => w=0
                    float s = fma_sat(a.z, cnz[c], fmaf(a.y, cny[c], a.x * cnx[c]));
                    float lg = lg2a(s);
                    // depth term: |z_t - z_c| * min(rr_c * (1/dist), 1e4*log2e)
                    float t    = fabsf(a.w - cz[c]);
                    float rden = fminf(crr[c] * (l ? T.w : T.z), RDEN_CLAMP);
                    // w = exp2( cxy + 128*lg - t*rden )
                    float arg = fmaf(lg, 128.0f, l ? T.y : T.x);
                    arg = fmaf(-t, rden, arg);
                    w[c] = ex2a(arg);
                }
                unsigned long long w2 = pk(w[2 * p], w[2 * p + 1]);
                aw2[p] = f2add(aw2[p], w2);
                ar2[p] = f2fma(cr2, w2, ar2[p]);
                ag2[p] = f2fma(cg2, w2, ag2[p]);
                ab2[p] = f2fma(cb2, w2, ab2[p]);
            }
        }
    }

    // write out: out[(gy*W+gx)*3 + ch] = acc_col / max(acc_w, eps)
    const int gx  = blockIdx.x * TILE + tix;
    const int gyb = blockIdx.y * TILE + tidy4;
#pragma unroll
    for (int p = 0; p < 2; ++p) {
        float w0, w1, r0, r1, q0, q1, b0, b1;
        upk(aw2[p], w0, w1);
        upk(ar2[p], r0, r1);
        upk(ag2[p], q0, q1);
        upk(ab2[p], b0, b1);
        int gy = gyb + 2 * p;
        if (gy < IH) {
            float inv = rcpa(fmaxf(w0, FEPS));
            float* o = out + ((size_t)gy * IW + gx) * 3;
            o[0] = r0 * inv; o[1] = q0 * inv; o[2] = b0 * inv;
        }
        if (gy + 1 < IH) {
            float inv = rcpa(fmaxf(w1, FEPS));
            float* o = out + ((size_t)(gy + 1) * IW + gx) * 3;
            o[0] = r1 * inv; o[1] = q1 * inv; o[2] = b1 * inv;
        }
    }
}

extern "C" void kernel_launch(void* const* d_in, const int* in_sizes, int n_in,
                              void* d_out, int out_size) {
    (void)in_sizes; (void)n_in; (void)out_size;
    const float* in = (const float*)d_in[0];
    float* out = (float*)d_out;

    repack_kernel<<<(IH * IW + 255) / 256, 256>>>(in);

    const int smem = (SWID * SWID * 2 + TABN) * (int)sizeof(float4);
    cudaFuncSetAttribute(bilateral_kernel,
                         cudaFuncAttributeMaxDynamicSharedMemorySize, smem);
    dim3 blk(32, 8);
    dim3 grd(IW / TILE, (IH + TILE - 1) / TILE);
    bilateral_kernel<<<grd, blk, smem>>>(out);
}

// round 17
// speedup vs baseline: 1.7973x; 1.1856x over previous
#include <cuda_runtime.h>

// ---------------------------------------------------------------------------
// BilateralDenoiser: 15x15 cross-bilateral filter (SIGMA=1 -> N=7)
//   w = exp(-d^2/2) * clip(nrm_t . nrm_c, eps, 1)^128
//       * exp(-|z_t - z_c| / max(dz_c * d, eps)),  zero outside image.
// R14: disc truncation QMAX=40 -> 242us kernel, err 4.8e-7. Calibration:
//      rel_err ~= 17 * dropped Gaussian mass.
// R15: QMAX=29 (extra mass 9.2e-7 -> predicted err ~1.6e-5, 60x margin).
//      Trips 168 -> 130, HALO 6 -> 5 (SWID 42). Color plane stored as float3
//      in smem (rr for centers from global) -> 53.2KB -> 4 CTAs/SM, 32 warps.
// ---------------------------------------------------------------------------

#define IH 1080
#define IW 1920
#define ICH 11
#define TILE 32
#define HALO 5
#define SWID 42          // TILE + 2*HALO
#define TABN (16 * 15)   // s in [0,15], dx slot in [0,14]
#define FEPS 1e-4f
#define QMAX 29
#define RDEN_CLAMP 14426.950408889634f   // 1e4 * log2(e)
#define F32_INF __int_as_float(0x7f800000)

__device__ float4 g_A[IH * IW];  // nrm.x, nrm.y, nrm.z, z
__device__ float4 g_B[IH * IW];  // col.r, col.g, col.b, rr (= log2e/dz or +inf)

// ---------------- helpers ---------------------------------------------------
__device__ __forceinline__ unsigned long long pk(float lo, float hi) {
    unsigned long long r;
    asm("mov.b64 %0, {%1, %2};" : "=l"(r)
        : "r"(__float_as_uint(lo)), "r"(__float_as_uint(hi)));
    return r;
}
__device__ __forceinline__ void upk(unsigned long long v, float& lo, float& hi) {
    unsigned int a, b;
    asm("mov.b64 {%0, %1}, %2;" : "=r"(a), "=r"(b) : "l"(v));
    lo = __uint_as_float(a); hi = __uint_as_float(b);
}
__device__ __forceinline__ unsigned long long f2add(unsigned long long a, unsigned long long b) {
    unsigned long long d;
    asm("add.rn.f32x2 %0, %1, %2;" : "=l"(d) : "l"(a), "l"(b));
    return d;
}
__device__ __forceinline__ unsigned long long f2fma(unsigned long long a, unsigned long long b,
                                                    unsigned long long c) {
    unsigned long long d;
    asm("fma.rn.f32x2 %0, %1, %2, %3;" : "=l"(d) : "l"(a), "l"(b), "l"(c));
    return d;
}
__device__ __forceinline__ float fma_sat(float a, float b, float c) {
    float d;
    asm("fma.rn.sat.f32 %0, %1, %2, %3;" : "=f"(d) : "f"(a), "f"(b), "f"(c));
    return d;
}
__device__ __forceinline__ float rcpa(float x) {
    float y; asm("rcp.approx.f32 %0, %1;" : "=f"(y) : "f"(x)); return y;
}
__device__ __forceinline__ float ex2a(float x) {
    float y; asm("ex2.approx.f32 %0, %1;" : "=f"(y) : "f"(x)); return y;
}
__device__ __forceinline__ float lg2a(float x) {
    float y; asm("lg2.approx.f32 %0, %1;" : "=f"(y) : "f"(x)); return y;
}

// ---------------- repack: AoS(11ch) -> two float4 SoA buffers ----------------
__global__ void repack_kernel(const float* __restrict__ in) {
    int i = blockIdx.x * blockDim.x + threadIdx.x;
    if (i >= IH * IW) return;
    const float* p = in + (size_t)i * ICH;
    float dz = p[10];
    float rr = (dz > 0.0f) ? rcpa(dz) * 1.4426950408889634f : F32_INF;
    g_A[i] = make_float4(p[3], p[4], p[5], p[9]);
    g_B[i] = make_float4(p[0], p[1], p[2], rr);
}

// ---------------- main tiled kernel: 32x32 outputs / CTA, PY=4 per thread ---
__global__ void __launch_bounds__(256, 4)
bilateral_kernel(float* __restrict__ out) {
    extern __shared__ unsigned char smraw[];
    float4* sA   = reinterpret_cast<float4*>(smraw);                 // 42^2 * 16
    float4* sTab = sA + SWID * SWID;                                  // 240 * 16
    float*  sC   = reinterpret_cast<float*>(sTab + TABN);            // 42^2 * 12

    const int tix  = threadIdx.x;
    const int tidy = threadIdx.y;
    const int tid  = tidy * 32 + tix;
    const int gx0  = blockIdx.x * TILE - HALO;
    const int gy0  = blockIdx.y * TILE - HALO;

    // fill 42x42 halo tile; OOB pixels -> zeros (nrm=0 => weight exactly 0)
    for (int i = tid; i < SWID * SWID; i += 256) {
        int ly = i / SWID, lx = i - ly * SWID;
        int gy = gy0 + ly, gx = gx0 + lx;
        float4 a = make_float4(0.f, 0.f, 0.f, 0.f);
        float4 b = a;
        if ((unsigned)gy < (unsigned)IH && (unsigned)gx < (unsigned)IW) {
            int g = gy * IW + gx;
            a = g_A[g]; b = g_B[g];
        }
        sA[i] = a;
        sC[i * 3 + 0] = b.x; sC[i * 3 + 1] = b.y; sC[i * 3 + 2] = b.z;
    }
    // per-(s,dx) table. entry s covers lane pair (dyA=s-7, dyB=s-8).
    //   cxy = -q*log2e/2  (q = dy^2+dx^2), or -1e30 (kills weight) if q>QMAX
    //   rd  = 1/dist (1e4 at dist=0 center tap; fmin clamp absorbs it)
    for (int i = tid; i < TABN; i += 256) {
        int s = i / 15, dxi = i - s * 15;
        float dx = (float)(dxi - 7);
        int dyA = s - 7, dyB = s - 8;
        float qA = dyA * dyA + dx * dx, qB = dyB * dyB + dx * dx;
        bool vA = qA <= (float)QMAX;
        bool vB = qB <= (float)QMAX;
        float cA = vA ? -qA * 0.72134752044f : -1e30f;
        float cB = vB ? -qB * 0.72134752044f : -1e30f;
        float rA = (vA && qA > 0.f) ? rsqrtf(qA) : 1e4f;
        float rB = (vB && qB > 0.f) ? rsqrtf(qB) : 1e4f;
        sTab[i] = make_float4(cA, cB, rA, rB);
    }
    __syncthreads();

    // center data for 4 rows: c = 0..3 (pair p holds centers 2p, 2p+1)
    const int tidy4 = tidy * 4;
    const int gx    = blockIdx.x * TILE + tix;
    const int gyb   = blockIdx.y * TILE + tidy4;
    float cnx[4], cny[4], cnz[4], cz[4], crr[4];
#pragma unroll
    for (int c = 0; c < 4; ++c) {
        int r = tidy4 + c + HALO;
        float4 a = sA[r * SWID + tix + HALO];
        cnx[c] = a.x; cny[c] = a.y; cnz[c] = a.z; cz[c] = a.w;
        int cy = gyb + c; if (cy > IH - 1) cy = IH - 1;   // clamp (OOB rows unused)
        crr[c] = __ldg(&g_B[cy * IW + gx].w);
    }
    unsigned long long ar2[2] = {0ull, 0ull}, ag2[2] = {0ull, 0ull};
    unsigned long long ab2[2] = {0ull, 0ull}, aw2[2] = {0ull, 0ull};

    // disc windows (q <= 29): dymax per |dx|: 0,1,2 -> 5; 3 -> 4; 4 -> 3; 5 -> 2
    // dxi = 2..12 (dx = -5..5); ntrip = 2*dymax+4 covers the 4-lane footprint.
    const int rowbase = tidy4 * SWID + tix;
#pragma unroll 1
    for (int dxi = 2; dxi <= 12; ++dxi) {
        int adx = (dxi >= 7) ? dxi - 7 : 7 - dxi;       // |dx| in 0..5
        int dymax = (adx <= 2) ? 5 : (adx == 3 ? 4 : (adx == 4 ? 3 : 2));
        int ylo   = HALO - dymax;
        int ntrip = 2 * dymax + 4;
#pragma unroll 2
        for (int k = 0; k < ntrip; ++k) {
            int nyi = ylo + k;
            int idx = rowbase + nyi * SWID + (dxi - 2);
            float4 a = sA[idx];                 // nx, ny, nz, z
            float br = sC[idx * 3 + 0];
            float bg = sC[idx * 3 + 1];
            float bb = sC[idx * 3 + 2];
            unsigned long long cr2 = pk(br, br);
            unsigned long long cg2 = pk(bg, bg);
            unsigned long long cb2 = pk(bb, bb);
            float4 T0 = sTab[(nyi + 2) * 15 + dxi];  // pair 0: dy = nyi-5, nyi-6
            float4 T1 = sTab[nyi * 15 + dxi];        // pair 1: dy = nyi-7, nyi-8

            float w[4];
#pragma unroll
            for (int p = 0; p < 2; ++p) {
                const float4& T = p ? T1 : T0;
#pragma unroll
                for (int l = 0; l < 2; ++l) {
                    int c = 2 * p + l;
                    // normal term: 128*lg2(sat(dot)); sat->0 => lg2->-inf => w=0
                    float s = fma_sat(a.z, cnz[c], fmaf(a.y, cny[c], a.x * cnx[c]));
                    float lg = lg2a(s);
                    // depth term: |z_t - z_c| * min(rr_c * (1/dist), 1e4*log2e)
                    float t    = fabsf(a.w - cz[c]);
                    float rden = fminf(crr[c] * (l ? T.w : T.z), RDEN_CLAMP);
                    // w = exp2( cxy + 128*lg - t*rden )
                    float arg = fmaf(lg, 128.0f, l ? T.y : T.x);
                    arg = fmaf(-t, rden, arg);
                    w[c] = ex2a(arg);
                }
                unsigned long long w2 = pk(w[2 * p], w[2 * p + 1]);
                aw2[p] = f2add(aw2[p], w2);
                ar2[p] = f2fma(cr2, w2, ar2[p]);
                ag2[p] = f2fma(cg2, w2, ag2[p]);
                ab2[p] = f2fma(cb2, w2, ab2[p]);
            }
        }
    }

    // write out: out[(gy*W+gx)*3 + ch] = acc_col / max(acc_w, eps)
#pragma unroll
    for (int p = 0; p < 2; ++p) {
        float w0, w1, r0, r1, q0, q1, b0, b1;
        upk(aw2[p], w0, w1);
        upk(ar2[p], r0, r1);
        upk(ag2[p], q0, q1);
        upk(ab2[p], b0, b1);
        int gy = gyb + 2 * p;
        if (gy < IH) {
            float inv = rcpa(fmaxf(w0, FEPS));
            float* o = out + ((size_t)gy * IW + gx) * 3;
            o[0] = r0 * inv; o[1] = q0 * inv; o[2] = b0 * inv;
        }
        if (gy + 1 < IH) {
            float inv = rcpa(fmaxf(w1, FEPS));
            float* o = out + ((size_t)(gy + 1) * IW + gx) * 3;
            o[0] = r1 * inv; o[1] = q1 * inv; o[2] = b1 * inv;
        }
    }
}

extern "C" void kernel_launch(void* const* d_in, const int* in_sizes, int n_in,
                              void* d_out, int out_size) {
    (void)in_sizes; (void)n_in; (void)out_size;
    const float* in = (const float*)d_in[0];
    float* out = (float*)d_out;

    repack_kernel<<<(IH * IW + 255) / 256, 256>>>(in);

    const int smem = SWID * SWID * (int)sizeof(float4)        // sA
                   + TABN * (int)sizeof(float4)               // sTab
                   + SWID * SWID * 3 * (int)sizeof(float);    // sC
    cudaFuncSetAttribute(bilateral_kernel,
                         cudaFuncAttributeMaxDynamicSharedMemorySize, smem);
    dim3 blk(32, 8);
    dim3 grd(IW / TILE, (IH + TILE - 1) / TILE);
    bilateral_kernel<<<grd, blk, smem>>>(out);
}